// round 1
// baseline (speedup 1.0000x reference)
#include <cuda_runtime.h>

#define NN 1024
#define BB 32
#define FF 32
#define DD 64
#define HH 64
#define CC 2048   // B*D
#define NP1 1025

// ---------------- scratch (static __device__, no allocs) ----------------
__device__ float g_Abin[NN * NN];     // binarized adjacency
__device__ float g_mu1b[NN * CC];     // mu_1 in [n][b][d]
__device__ float g_mu[NN * CC];       // current mu in [n][b][d]
__device__ float g_pool[NN * CC];     // A @ mu
__device__ float g_mu3[NN * DD];      // batch-independent mu3
__device__ float g_part[16 * CC];     // column-sum partials
__device__ float g_mumean[BB * DD];
__device__ float g_s2[BB * HH];

// ---------------- binarize adjacency ----------------
__global__ __launch_bounds__(256) void k_binarize(const float* __restrict__ adj) {
    int i = blockIdx.x * 256 + threadIdx.x;   // over float4s
    float4 v = ((const float4*)adj)[i];
    float4 r;
    r.x = v.x > 0.f ? 1.f : 0.f;
    r.y = v.y > 0.f ? 1.f : 0.f;
    r.z = v.z > 0.f ? 1.f : 0.f;
    r.w = v.w > 0.f ? 1.f : 0.f;
    ((float4*)g_Abin)[i] = r;
}

// ---------------- mu_1 = relu(xv @ mu1), written in [n][b][d]; also init g_mu ----------------
__global__ __launch_bounds__(256) void k_mu1(const float* __restrict__ xv,
                                             const float* __restrict__ mu1w) {
    int n = blockIdx.x;
    __shared__ float xs[BB][FF];
    __shared__ float ws[FF][DD];
    int tid = threadIdx.x;
    for (int i = tid; i < BB * FF; i += 256) {
        int b = i / FF, f = i % FF;
        xs[b][f] = xv[(b * NN + n) * FF + f];
    }
    for (int i = tid; i < FF * DD; i += 256) ws[i / DD][i % DD] = mu1w[i];
    __syncthreads();
#pragma unroll
    for (int j = 0; j < 8; j++) {
        int c = tid + 256 * j;
        int b = c >> 6, d = c & 63;
        float acc = 0.f;
#pragma unroll
        for (int f = 0; f < FF; f++) acc += xs[b][f] * ws[f][d];
        float r = fmaxf(acc, 0.f);
        g_mu1b[n * CC + c] = r;
        g_mu[n * CC + c]   = r;   // mu at t=0
    }
}

// ---------------- mu3[n][d2] = (sum_m relu(adj[n,m]*W4 + b4)) @ W3^T + b3 ----------------
__global__ __launch_bounds__(256) void k_mu3(const float* __restrict__ adj,
                                             const float* __restrict__ W4,
                                             const float* __restrict__ b4,
                                             const float* __restrict__ W3,
                                             const float* __restrict__ b3) {
    int n = blockIdx.x;
    int tid = threadIdx.x;
    int d = tid & 63, q = tid >> 6;
    float w = W4[d], c0 = b4[d];
    float acc = 0.f;
    const float* arow = adj + n * NN;
    for (int m = q; m < NN; m += 4)
        acc += fmaxf(arow[m] * w + c0, 0.f);
    __shared__ float part[4][DD];
    __shared__ float mu4s[DD];
    part[q][d] = acc;
    __syncthreads();
    if (tid < DD) mu4s[tid] = part[0][tid] + part[1][tid] + part[2][tid] + part[3][tid];
    __syncthreads();
    if (tid < DD) {
        int d2 = tid;
        float a = b3[d2];
#pragma unroll
        for (int e = 0; e < DD; e++) a += mu4s[e] * W3[d2 * DD + e];
        g_mu3[n * DD + d2] = a;
    }
}

// ---------------- pool = A_bin(1024x1024) @ mu(1024x2048), 64x64x32 tiles ----------------
__global__ __launch_bounds__(256) void k_pool() {
    __shared__ float As[32][65];   // transposed A tile, padded
    __shared__ float Bs[32][64];
    int tid = threadIdx.x;
    int bm = blockIdx.y * 64;      // rows (n)
    int bn = blockIdx.x * 64;      // cols (b*64+d)
    int tx = tid & 15, ty = tid >> 4;
    float acc[4][4] = {};
    const float* Ab = g_Abin + bm * NN;
    const float* Bb = g_mu + bn;

    for (int k0 = 0; k0 < NN; k0 += 32) {
#pragma unroll
        for (int t = 0; t < 2; t++) {
            int v = tid + t * 256;
            int r = v >> 3, c4 = (v & 7) << 2;
            float4 a4 = *(const float4*)(Ab + r * NN + k0 + c4);
            As[c4 + 0][r] = a4.x;
            As[c4 + 1][r] = a4.y;
            As[c4 + 2][r] = a4.z;
            As[c4 + 3][r] = a4.w;
        }
#pragma unroll
        for (int t = 0; t < 2; t++) {
            int v = tid + t * 256;
            int r = v >> 4, c4 = (v & 15) << 2;
            *(float4*)(&Bs[r][c4]) = *(const float4*)(Bb + (k0 + r) * CC + c4);
        }
        __syncthreads();
#pragma unroll
        for (int k = 0; k < 32; k++) {
            float a0 = As[k][ty * 4 + 0];
            float a1 = As[k][ty * 4 + 1];
            float a2 = As[k][ty * 4 + 2];
            float a3 = As[k][ty * 4 + 3];
            float4 bv = *(const float4*)(&Bs[k][tx << 2]);
            acc[0][0] += a0 * bv.x; acc[0][1] += a0 * bv.y; acc[0][2] += a0 * bv.z; acc[0][3] += a0 * bv.w;
            acc[1][0] += a1 * bv.x; acc[1][1] += a1 * bv.y; acc[1][2] += a1 * bv.z; acc[1][3] += a1 * bv.w;
            acc[2][0] += a2 * bv.x; acc[2][1] += a2 * bv.y; acc[2][2] += a2 * bv.z; acc[2][3] += a2 * bv.w;
            acc[3][0] += a3 * bv.x; acc[3][1] += a3 * bv.y; acc[3][2] += a3 * bv.z; acc[3][3] += a3 * bv.w;
        }
        __syncthreads();
    }
#pragma unroll
    for (int i = 0; i < 4; i++) {
        int row = bm + ty * 4 + i;
        float4 o = make_float4(acc[i][0], acc[i][1], acc[i][2], acc[i][3]);
        *(float4*)(&g_pool[row * CC + bn + (tx << 2)]) = o;
    }
}

// ---------------- mu = relu(mu_1 + pool @ W2^T + mu3) ----------------
__global__ __launch_bounds__(256) void k_combine(const float* __restrict__ W2) {
    int n = blockIdx.x;
    __shared__ float W2t[DD][DD + 1];   // W2t[e][d] = W2[d][e]
    __shared__ float mu3s[DD];
    __shared__ float ps[4][DD];
    int tid = threadIdx.x;
    for (int i = tid; i < DD * DD; i += 256) {
        int d = i >> 6, e = i & 63;
        W2t[e][d] = W2[i];
    }
    if (tid < DD) mu3s[tid] = g_mu3[n * DD + tid];
    int bb = tid >> 6, d = tid & 63;
    const float* pr  = g_pool + n * CC;
    const float* m1r = g_mu1b + n * CC;
    float* mr = g_mu + n * CC;
    for (int b0 = 0; b0 < BB; b0 += 4) {
        __syncthreads();
        ps[bb][d] = pr[(b0 + bb) * DD + d];
        __syncthreads();
        float acc = mu3s[d] + m1r[(b0 + bb) * DD + d];
#pragma unroll
        for (int e = 0; e < DD; e++) acc += ps[bb][e] * W2t[e][d];
        mr[(b0 + bb) * DD + d] = fmaxf(acc, 0.f);
    }
}

// ---------------- partial column sums of mu over n ----------------
__global__ __launch_bounds__(256) void k_colsum() {
    int c = blockIdx.x * 256 + threadIdx.x;   // grid.x = 8
    int g = blockIdx.y;                       // 16 chunks of 64 rows
    float s = 0.f;
    int n0 = g * 64;
#pragma unroll 8
    for (int n = n0; n < n0 + 64; n++) s += g_mu[n * CC + c];
    g_part[g * CC + c] = s;
}

// ---------------- mumean + s2 (single block) ----------------
__global__ __launch_bounds__(256) void k_small(const float* __restrict__ option,
                                               const float* __restrict__ Wq1,
                                               const float* __restrict__ bq1,
                                               const float* __restrict__ Wq2,
                                               const float* __restrict__ bq2,
                                               const float* __restrict__ Wreg) {
    __shared__ float msum[CC];
    int tid = threadIdx.x;
    for (int c = tid; c < CC; c += 256) {
        float s = 0.f;
#pragma unroll
        for (int g = 0; g < 16; g++) s += g_part[g * CC + c];
        msum[c] = s;
    }
    __syncthreads();
    const float inv = 1.0f / (float)NN;
    for (int c = tid; c < CC; c += 256) {
        int b = c >> 6, d2 = c & 63;
        float acc = bq1[d2];
#pragma unroll
        for (int e = 0; e < DD; e++) acc += msum[b * DD + e] * inv * Wq1[d2 * DD + e];
        g_mumean[c] = fmaxf(acc, 0.f);
        // s2[b][h]: option-branch contribution to the regression layer
        float opt = option[b];
        float acc2 = 0.f;
        int h = d2;
#pragma unroll
        for (int j = 0; j < DD; j++)
            acc2 += (opt * Wq2[j] + bq2[j]) * Wreg[h * (2 * DD) + DD + j];
        g_s2[c] = acc2;
    }
}

// ---------------- final head: out[b, i] ----------------
__global__ __launch_bounds__(256) void k_final(const float* __restrict__ Wreg,
                                               const float* __restrict__ breg,
                                               const float* __restrict__ Wq,
                                               const float* __restrict__ bq,
                                               float* __restrict__ out) {
    int b = blockIdx.y;
    int tile = blockIdx.x;    // 17 tiles of 64 rows
    __shared__ float Wr[HH][DD + 1];   // first half of Wreg
    __shared__ float wqs[HH], s2s[HH], brs[HH];
    __shared__ float vs[8][DD];
    int tid = threadIdx.x;
    for (int i = tid; i < HH * DD; i += 256) {
        int h = i >> 6, j = i & 63;
        Wr[h][j] = Wreg[h * (2 * DD) + j];
    }
    if (tid < HH) {
        wqs[tid] = Wq[tid];
        s2s[tid] = g_s2[b * HH + tid];
        brs[tid] = breg[tid];
    }
    __syncthreads();
    int w = tid >> 5, lane = tid & 31;
    float bqv = bq[0];
    for (int s = 0; s < 8; s++) {
        int i = tile * 64 + w * 8 + s;
        if (i > NN) continue;   // warp-uniform
        const float* vptr = (i < NN) ? (g_mu + i * CC + b * DD) : (g_mumean + b * DD);
        vs[w][lane]      = vptr[lane];
        vs[w][lane + 32] = vptr[lane + 32];
        __syncwarp();
        float r = 0.f;
#pragma unroll
        for (int hh = 0; hh < 2; hh++) {
            int h = lane + hh * 32;
            float accd = s2s[h] + brs[h];
#pragma unroll
            for (int j = 0; j < DD; j++) accd += vs[w][j] * Wr[h][j];
            r += fmaxf(accd, 0.f) * wqs[h];
        }
#pragma unroll
        for (int off = 16; off; off >>= 1) r += __shfl_down_sync(0xffffffff, r, off);
        if (lane == 0) out[b * NP1 + i] = r + bqv;
        __syncwarp();
    }
}

// ---------------- launch ----------------
extern "C" void kernel_launch(void* const* d_in, const int* in_sizes, int n_in,
                              void* d_out, int out_size) {
    const float* xv     = (const float*)d_in[0];
    const float* option = (const float*)d_in[1];
    const float* adj    = (const float*)d_in[2];
    const float* mu1w   = (const float*)d_in[3];
    const float* W2     = (const float*)d_in[4];
    // b2 = d_in[5] (all zeros in setup, but we keep generality: b2 is folded
    // into nothing — reference adds b2; include it via mu3? No: add explicitly)
    const float* W3     = (const float*)d_in[6];
    const float* b3     = (const float*)d_in[7];
    const float* W4     = (const float*)d_in[8];
    const float* b4     = (const float*)d_in[9];
    const float* Wq1    = (const float*)d_in[10];
    const float* bq1    = (const float*)d_in[11];
    const float* Wq2    = (const float*)d_in[12];
    const float* bq2    = (const float*)d_in[13];
    const float* Wreg   = (const float*)d_in[14];
    const float* breg   = (const float*)d_in[15];
    const float* Wq     = (const float*)d_in[16];
    const float* bq     = (const float*)d_in[17];
    float* out = (float*)d_out;
    (void)in_sizes; (void)n_in; (void)out_size;

    k_binarize<<<NN * NN / 4 / 256, 256>>>(adj);
    k_mu1<<<NN, 256>>>(xv, mu1w);
    k_mu3<<<NN, 256>>>(adj, W4, b4, W3, b3);
    for (int t = 1; t < 4; t++) {
        k_pool<<<dim3(CC / 64, NN / 64), 256>>>();
        k_combine<<<NN, 256>>>(W2);
    }
    k_colsum<<<dim3(8, 16), 256>>>();
    k_small<<<1, 256>>>(option, Wq1, bq1, Wq2, bq2, Wreg);
    k_final<<<dim3(17, BB), 256>>>(Wreg, breg, Wq, bq, out);
}

// round 3
// speedup vs baseline: 2.3950x; 2.3950x over previous
#include <cuda_runtime.h>
#include <cuda_bf16.h>
#include <cstdint>

#define NN 1024
#define BB 32
#define FF 32
#define DD 64
#define HH 64
#define CC 2048   // B*D
#define NP1 1025

// ---------------- scratch (static __device__, no allocs) ----------------
__device__ __nv_bfloat16 g_Abf[NN * NN];    // binarized adjacency, bf16 (exact 0/1)
__device__ float g_m13[NN * CC];            // mu_1 + mu3 + b2
__device__ float g_mu[NN * CC];             // current mu (fp32), [n][b*64+d]
__device__ __nv_bfloat16 g_nu_hi[NN * CC];  // hi part of nu = mu @ W2^T
__device__ __nv_bfloat16 g_nu_lo[NN * CC];  // lo part
__device__ float g_mu3[NN * DD];
__device__ float g_part[16 * CC];
__device__ float g_mumean[BB * DD];
__device__ float g_s2[BB * HH];

// ---------------- helpers ----------------
__device__ __forceinline__ uint32_t smem_u32(const void* p) {
    uint32_t a;
    asm("{ .reg .u64 t; cvta.to.shared.u64 t, %1; cvt.u32.u64 %0, t; }" : "=r"(a) : "l"(p));
    return a;
}
__device__ __forceinline__ void cp16(uint32_t saddr, const void* gaddr) {
    asm volatile("cp.async.cg.shared.global [%0], [%1], 16;\n" :: "r"(saddr), "l"(gaddr));
}

// ---------------- adjacency -> bf16 binary ----------------
__global__ __launch_bounds__(256) void k_prep(const float* __restrict__ adj) {
    int i = blockIdx.x * 256 + threadIdx.x;   // group of 8 elems
    const float4* a = (const float4*)adj + i * 2;
    float4 v0 = a[0], v1 = a[1];
    uint4 out;
    __nv_bfloat16* r = (__nv_bfloat16*)&out;
    r[0] = __float2bfloat16(v0.x > 0.f ? 1.f : 0.f);
    r[1] = __float2bfloat16(v0.y > 0.f ? 1.f : 0.f);
    r[2] = __float2bfloat16(v0.z > 0.f ? 1.f : 0.f);
    r[3] = __float2bfloat16(v0.w > 0.f ? 1.f : 0.f);
    r[4] = __float2bfloat16(v1.x > 0.f ? 1.f : 0.f);
    r[5] = __float2bfloat16(v1.y > 0.f ? 1.f : 0.f);
    r[6] = __float2bfloat16(v1.z > 0.f ? 1.f : 0.f);
    r[7] = __float2bfloat16(v1.w > 0.f ? 1.f : 0.f);
    ((uint4*)g_Abf)[i] = out;
}

// ---------------- mu3[n][d2] ----------------
__global__ __launch_bounds__(256) void k_mu3(const float* __restrict__ adj,
                                             const float* __restrict__ W4,
                                             const float* __restrict__ b4,
                                             const float* __restrict__ W3,
                                             const float* __restrict__ b3) {
    int n = blockIdx.x;
    int tid = threadIdx.x;
    int d = tid & 63, q = tid >> 6;
    float w = W4[d], c0 = b4[d];
    float acc = 0.f;
    const float* arow = adj + n * NN;
    for (int m = q; m < NN; m += 4)
        acc += fmaxf(arow[m] * w + c0, 0.f);
    __shared__ float part[4][DD];
    __shared__ float mu4s[DD];
    part[q][d] = acc;
    __syncthreads();
    if (tid < DD) mu4s[tid] = part[0][tid] + part[1][tid] + part[2][tid] + part[3][tid];
    __syncthreads();
    if (tid < DD) {
        int d2 = tid;
        float a = b3[d2];
#pragma unroll
        for (int e = 0; e < DD; e++) a += mu4s[e] * W3[d2 * DD + e];
        g_mu3[n * DD + d2] = a;
    }
}

// ---------------- mu_1 = relu(xv @ mu1); g_mu = mu_1; g_m13 = mu_1 + mu3 + b2 ----------------
__global__ __launch_bounds__(256) void k_mu1(const float* __restrict__ xv,
                                             const float* __restrict__ mu1w,
                                             const float* __restrict__ b2) {
    int n = blockIdx.x;
    __shared__ float xs[BB][FF];
    __shared__ float ws[FF][DD];
    __shared__ float m3[DD];
    int tid = threadIdx.x;
    for (int i = tid; i < BB * FF; i += 256) {
        int b = i / FF, f = i % FF;
        xs[b][f] = xv[(b * NN + n) * FF + f];
    }
    for (int i = tid; i < FF * DD; i += 256) ws[i / DD][i % DD] = mu1w[i];
    if (tid < DD) m3[tid] = g_mu3[n * DD + tid] + b2[tid];
    __syncthreads();
#pragma unroll
    for (int j = 0; j < 8; j++) {
        int c = tid + 256 * j;
        int b = c >> 6, d = c & 63;
        float acc = 0.f;
#pragma unroll
        for (int f = 0; f < FF; f++) acc += xs[b][f] * ws[f][d];
        float r = fmaxf(acc, 0.f);
        g_mu[n * CC + c] = r;
        g_m13[n * CC + c] = r + m3[d];
    }
}

// ---------------- nu = mu @ W2^T (per-b 64x64), emit hi/lo bf16 ----------------
__global__ __launch_bounds__(256) void k_nu(const float* __restrict__ W2) {
    int n = blockIdx.x;
    __shared__ float W2t[DD][DD + 1];   // W2t[e][d] = W2[d][e]
    __shared__ float mus[CC];
    int tid = threadIdx.x;
    for (int i = tid; i < DD * DD; i += 256) W2t[i & 63][i >> 6] = W2[i];
    for (int i = tid; i < CC / 4; i += 256)
        ((float4*)mus)[i] = ((const float4*)(g_mu + n * CC))[i];
    __syncthreads();
    int b4i = tid >> 6, d = tid & 63;
    for (int b0 = 0; b0 < BB; b0 += 4) {
        int b = b0 + b4i;
        float acc = 0.f;
#pragma unroll
        for (int e = 0; e < DD; e++) acc += mus[b * DD + e] * W2t[e][d];
        __nv_bfloat16 h = __float2bfloat16(acc);
        float lo = acc - __bfloat162float(h);
        g_nu_hi[n * CC + b * DD + d] = h;
        g_nu_lo[n * CC + b * DD + d] = __float2bfloat16(lo);
    }
}

// ---------------- pool = A @ nu via mma.sync bf16 (hi/lo); mu = relu(m13 + pool) ----------------
// CTA tile 128(m) x 128(c), K-chunk 32, double-buffered cp.async, 8 warps (2x4).
__global__ __launch_bounds__(256) void k_mma() {
    __shared__ __align__(16) char As[2][8192];   // A: 128 rows x 32 k bf16, swizzled
    __shared__ __align__(16) char Bh[2][8192];   // Bh: 32 k x 128 c bf16, swizzled
    __shared__ __align__(16) char Bl[2][8192];

    int tid = threadIdx.x;
    int lane = tid & 31, wid = tid >> 5;
    int warpM = wid >> 2, warpN = wid & 3;
    int mbase = blockIdx.y * 128;
    int cbase = blockIdx.x * 128;

    float C[16][4];
#pragma unroll
    for (int i = 0; i < 16; i++)
#pragma unroll
        for (int j = 0; j < 4; j++) C[i][j] = 0.f;

    // per-thread load coordinates
    // A: unit i in [0,512): m = i>>2, u = i&3 (16B units of 8 bf16)
    // B: unit i in [0,512): k = i>>4, u = i&15
    uint32_t asb[2] = { smem_u32(&As[0][0]), smem_u32(&As[1][0]) };
    uint32_t bhb[2] = { smem_u32(&Bh[0][0]), smem_u32(&Bh[1][0]) };
    uint32_t blb[2] = { smem_u32(&Bl[0][0]), smem_u32(&Bl[1][0]) };

    auto load_stage = [&](int ch, int buf) {
#pragma unroll
        for (int t = 0; t < 2; t++) {
            int i = tid + t * 256;
            int m = i >> 2, u = i & 3;
            const __nv_bfloat16* g = g_Abf + (size_t)(mbase + m) * NN + ch * 32 + u * 8;
            uint32_t s = asb[buf] + m * 64 + (((u ^ ((m >> 1) & 3)) & 3) << 4);
            cp16(s, g);
        }
#pragma unroll
        for (int t = 0; t < 2; t++) {
            int i = tid + t * 256;
            int k = i >> 4, u = i & 15;
            int su = (u & 8) | ((u ^ k) & 7);
            size_t go = (size_t)(ch * 32 + k) * CC + cbase + u * 8;
            uint32_t so = k * 256 + (su << 4);
            cp16(bhb[buf] + so, g_nu_hi + go);
            cp16(blb[buf] + so, g_nu_lo + go);
        }
        asm volatile("cp.async.commit_group;\n" ::: "memory");
    };

    load_stage(0, 0);

    for (int ch = 0; ch < 32; ch++) {
        int buf = ch & 1;
        if (ch + 1 < 32) load_stage(ch + 1, buf ^ 1);
        if (ch + 1 < 32) asm volatile("cp.async.wait_group 1;\n" ::: "memory");
        else             asm volatile("cp.async.wait_group 0;\n" ::: "memory");
        __syncthreads();

#pragma unroll
        for (int ks = 0; ks < 2; ks++) {
            uint32_t a[4][4];
#pragma unroll
            for (int mt = 0; mt < 4; mt++) {
                int row = warpM * 64 + mt * 16 + (lane & 7) + ((lane >> 3) & 1) * 8;
                int unit = 2 * ks + (lane >> 4);
                uint32_t addr = asb[buf] + row * 64 + (((unit ^ ((row >> 1) & 3)) & 3) << 4);
                asm volatile("ldmatrix.sync.aligned.m8n8.x4.shared.b16 {%0,%1,%2,%3}, [%4];"
                             : "=r"(a[mt][0]), "=r"(a[mt][1]), "=r"(a[mt][2]), "=r"(a[mt][3])
                             : "r"(addr));
            }
            uint32_t bhf[4][2], blf[4][2];
#pragma unroll
            for (int pair = 0; pair < 2; pair++) {
                int k = ks * 16 + (lane & 7) + ((lane >> 3) & 1) * 8;
                int u = warpN * 4 + pair * 2 + (lane >> 4);
                int su = (u & 8) | ((u ^ k) & 7);
                uint32_t so = k * 256 + (su << 4);
                asm volatile("ldmatrix.sync.aligned.m8n8.x4.trans.shared.b16 {%0,%1,%2,%3}, [%4];"
                             : "=r"(bhf[pair * 2][0]), "=r"(bhf[pair * 2][1]),
                               "=r"(bhf[pair * 2 + 1][0]), "=r"(bhf[pair * 2 + 1][1])
                             : "r"(bhb[buf] + so));
                asm volatile("ldmatrix.sync.aligned.m8n8.x4.trans.shared.b16 {%0,%1,%2,%3}, [%4];"
                             : "=r"(blf[pair * 2][0]), "=r"(blf[pair * 2][1]),
                               "=r"(blf[pair * 2 + 1][0]), "=r"(blf[pair * 2 + 1][1])
                             : "r"(blb[buf] + so));
            }
#pragma unroll
            for (int mt = 0; mt < 4; mt++) {
#pragma unroll
                for (int nt = 0; nt < 4; nt++) {
                    float* c = C[mt * 4 + nt];
                    asm volatile(
                        "mma.sync.aligned.m16n8k16.row.col.f32.bf16.bf16.f32 "
                        "{%0,%1,%2,%3},{%4,%5,%6,%7},{%8,%9},{%0,%1,%2,%3};"
                        : "+f"(c[0]), "+f"(c[1]), "+f"(c[2]), "+f"(c[3])
                        : "r"(a[mt][0]), "r"(a[mt][1]), "r"(a[mt][2]), "r"(a[mt][3]),
                          "r"(bhf[nt][0]), "r"(bhf[nt][1]));
                    asm volatile(
                        "mma.sync.aligned.m16n8k16.row.col.f32.bf16.bf16.f32 "
                        "{%0,%1,%2,%3},{%4,%5,%6,%7},{%8,%9},{%0,%1,%2,%3};"
                        : "+f"(c[0]), "+f"(c[1]), "+f"(c[2]), "+f"(c[3])
                        : "r"(a[mt][0]), "r"(a[mt][1]), "r"(a[mt][2]), "r"(a[mt][3]),
                          "r"(blf[nt][0]), "r"(blf[nt][1]));
                }
            }
        }
        __syncthreads();
    }

    // epilogue: mu = relu(m13 + pool)
    int g = lane >> 2, tq = lane & 3;
#pragma unroll
    for (int mt = 0; mt < 4; mt++) {
#pragma unroll
        for (int nt = 0; nt < 4; nt++) {
            const float* c = C[mt * 4 + nt];
            int row0 = mbase + warpM * 64 + mt * 16 + g;
            int col = cbase + warpN * 32 + nt * 8 + tq * 2;
            {
                const float2 m = *(const float2*)(g_m13 + (size_t)row0 * CC + col);
                float2 o;
                o.x = fmaxf(m.x + c[0], 0.f);
                o.y = fmaxf(m.y + c[1], 0.f);
                *(float2*)(g_mu + (size_t)row0 * CC + col) = o;
            }
            {
                int row1 = row0 + 8;
                const float2 m = *(const float2*)(g_m13 + (size_t)row1 * CC + col);
                float2 o;
                o.x = fmaxf(m.x + c[2], 0.f);
                o.y = fmaxf(m.y + c[3], 0.f);
                *(float2*)(g_mu + (size_t)row1 * CC + col) = o;
            }
        }
    }
}

// ---------------- partial column sums of mu over n ----------------
__global__ __launch_bounds__(256) void k_colsum() {
    int c = blockIdx.x * 256 + threadIdx.x;
    int g = blockIdx.y;
    float s = 0.f;
    int n0 = g * 64;
#pragma unroll 8
    for (int n = n0; n < n0 + 64; n++) s += g_mu[n * CC + c];
    g_part[g * CC + c] = s;
}

// ---------------- mumean + s2, one block per b ----------------
__global__ __launch_bounds__(64) void k_small(const float* __restrict__ option,
                                              const float* __restrict__ Wq1,
                                              const float* __restrict__ bq1,
                                              const float* __restrict__ Wq2,
                                              const float* __restrict__ bq2,
                                              const float* __restrict__ Wreg) {
    int b = blockIdx.x, d = threadIdx.x;
    __shared__ float msum[DD];
    float s = 0.f;
#pragma unroll
    for (int g = 0; g < 16; g++) s += g_part[g * CC + b * DD + d];
    msum[d] = s * (1.0f / (float)NN);
    __syncthreads();
    float acc = bq1[d];
#pragma unroll
    for (int e = 0; e < DD; e++) acc += msum[e] * Wq1[d * DD + e];
    g_mumean[b * DD + d] = fmaxf(acc, 0.f);
    float opt = option[b];
    float acc2 = 0.f;
#pragma unroll
    for (int j = 0; j < DD; j++)
        acc2 += (opt * Wq2[j] + bq2[j]) * Wreg[d * (2 * DD) + DD + j];
    g_s2[b * HH + d] = acc2;
}

// ---------------- final head ----------------
__global__ __launch_bounds__(256) void k_final(const float* __restrict__ Wreg,
                                               const float* __restrict__ breg,
                                               const float* __restrict__ Wq,
                                               const float* __restrict__ bq,
                                               float* __restrict__ out) {
    int b = blockIdx.y;
    int tile = blockIdx.x;
    __shared__ float Wr[HH][DD + 1];
    __shared__ float wqs[HH], s2s[HH], brs[HH];
    __shared__ float vs[8][DD];
    int tid = threadIdx.x;
    for (int i = tid; i < HH * DD; i += 256) {
        int h = i >> 6, j = i & 63;
        Wr[h][j] = Wreg[h * (2 * DD) + j];
    }
    if (tid < HH) {
        wqs[tid] = Wq[tid];
        s2s[tid] = g_s2[b * HH + tid];
        brs[tid] = breg[tid];
    }
    __syncthreads();
    int w = tid >> 5, lane = tid & 31;
    float bqv = bq[0];
    for (int s = 0; s < 8; s++) {
        int i = tile * 64 + w * 8 + s;
        if (i > NN) continue;
        const float* vptr = (i < NN) ? (g_mu + i * CC + b * DD) : (g_mumean + b * DD);
        vs[w][lane]      = vptr[lane];
        vs[w][lane + 32] = vptr[lane + 32];
        __syncwarp();
        float r = 0.f;
#pragma unroll
        for (int hh = 0; hh < 2; hh++) {
            int h = lane + hh * 32;
            float accd = s2s[h] + brs[h];
#pragma unroll
            for (int j = 0; j < DD; j++) accd += vs[w][j] * Wr[h][j];
            r += fmaxf(accd, 0.f) * wqs[h];
        }
#pragma unroll
        for (int off = 16; off; off >>= 1) r += __shfl_down_sync(0xffffffff, r, off);
        if (lane == 0) out[b * NP1 + i] = r + bqv;
        __syncwarp();
    }
}

// ---------------- launch ----------------
extern "C" void kernel_launch(void* const* d_in, const int* in_sizes, int n_in,
                              void* d_out, int out_size) {
    const float* xv     = (const float*)d_in[0];
    const float* option = (const float*)d_in[1];
    const float* adj    = (const float*)d_in[2];
    const float* mu1w   = (const float*)d_in[3];
    const float* W2     = (const float*)d_in[4];
    const float* b2     = (const float*)d_in[5];
    const float* W3     = (const float*)d_in[6];
    const float* b3     = (const float*)d_in[7];
    const float* W4     = (const float*)d_in[8];
    const float* b4     = (const float*)d_in[9];
    const float* Wq1    = (const float*)d_in[10];
    const float* bq1    = (const float*)d_in[11];
    const float* Wq2    = (const float*)d_in[12];
    const float* bq2    = (const float*)d_in[13];
    const float* Wreg   = (const float*)d_in[14];
    const float* breg   = (const float*)d_in[15];
    const float* Wq     = (const float*)d_in[16];
    const float* bq     = (const float*)d_in[17];
    float* out = (float*)d_out;
    (void)in_sizes; (void)n_in; (void)out_size;

    k_prep<<<NN * NN / 8 / 256, 256>>>(adj);
    k_mu3<<<NN, 256>>>(adj, W4, b4, W3, b3);
    k_mu1<<<NN, 256>>>(xv, mu1w, b2);
    for (int t = 1; t < 4; t++) {
        k_nu<<<NN, 256>>>(W2);
        k_mma<<<dim3(CC / 128, NN / 128), 256>>>();
    }
    k_colsum<<<dim3(8, 16), 256>>>();
    k_small<<<32, 64>>>(option, Wq1, bq1, Wq2, bq2, Wreg);
    k_final<<<dim3(17, BB), 256>>>(Wreg, breg, Wq, bq, out);
}